// round 1
// baseline (speedup 1.0000x reference)
#include <cuda_runtime.h>
#include <math.h>

// Problem constants
#define B_  32
#define J_  1024
#define D_  192
#define E_  384
#define N_  16
#define R_  (B_ * J_)          // 32768 rows
#define RE_ (R_ * E_)          // 12,582,912

// ---------------- scratch (static device globals; no runtime alloc) ----------
__device__ float g_t[R_ * D_];        // LayerNorm output
__device__ float g_x[R_ * E_];        // x = t@Wx + bx
__device__ float g_gate[R_ * E_];     // sigmoid(silu(z))
__device__ float g_xc[R_ * E_];       // conv output (per-direction, reused)
__device__ float g_bcdu[B_ * 64 * J_];// [b][c][j], c: 0-15 Bt,16-31 Ct,32-47 Draw,48-63 u
__device__ float g_S[R_ * N_];        // S_f + flip(S_b), (B,J,N)
__device__ float g_y[R_ * E_];        // gated readout

// ---------------- helpers -----------------------------------------------------
__device__ __forceinline__ float softplusf(float x) {
    return (x > 20.f) ? x : log1pf(expf(x));
}
__device__ __forceinline__ float sigmoidf_(float x) {
    return 1.f / (1.f + expf(-x));
}

// ---------------- K1: LayerNorm (warp per row, D=192 = 6*32) ------------------
__global__ void ln_kernel(const float* __restrict__ tokens,
                          const float* __restrict__ g,
                          const float* __restrict__ b) {
    int warp = (blockIdx.x * blockDim.x + threadIdx.x) >> 5;
    int lane = threadIdx.x & 31;
    if (warp >= R_) return;
    const float* row = tokens + warp * D_;
    float v[6];
    float sum = 0.f;
#pragma unroll
    for (int i = 0; i < 6; i++) { v[i] = row[lane + i * 32]; sum += v[i]; }
#pragma unroll
    for (int o = 16; o; o >>= 1) sum += __shfl_xor_sync(0xffffffffu, sum, o);
    float mu = sum * (1.f / D_);
    float sq = 0.f;
#pragma unroll
    for (int i = 0; i < 6; i++) { float d = v[i] - mu; sq += d * d; }
#pragma unroll
    for (int o = 16; o; o >>= 1) sq += __shfl_xor_sync(0xffffffffu, sq, o);
    float inv = rsqrtf(sq * (1.f / D_) + 1e-5f);
    float* out = g_t + warp * D_;
#pragma unroll
    for (int i = 0; i < 6; i++) {
        int c = lane + i * 32;
        out[c] = (v[i] - mu) * inv * g[c] + b[c];
    }
}

// ---------------- K2: GEMM t @ [Wx|Wz]  (M=32768, N=768, K=192) ---------------
// 64x64 tile, 256 threads, 4x4 microtile. Epilogue: x and gate.
__global__ void gemm_xz_kernel(const float* __restrict__ Wx,
                               const float* __restrict__ bx,
                               const float* __restrict__ Wz,
                               const float* __restrict__ bz) {
    const int BM = 64, BN = 64, BK = 32;
    __shared__ float As[BK][BM + 1];
    __shared__ float Bs[BK][BN];
    int bm = blockIdx.y * BM;
    int bn = blockIdx.x * BN;
    int tid = threadIdx.x;
    int tx = tid & 15, ty = tid >> 4;
    float acc[4][4] = {};
    for (int k0 = 0; k0 < D_; k0 += BK) {
#pragma unroll
        for (int i = tid; i < BM * BK; i += 256) {
            int m = i >> 5, k = i & 31;
            As[k][m] = g_t[(bm + m) * D_ + k0 + k];
        }
#pragma unroll
        for (int i = tid; i < BK * BN; i += 256) {
            int k = i >> 6, c = i & 63;
            int gc = bn + c;
            Bs[k][c] = (gc < E_) ? Wx[(k0 + k) * E_ + gc]
                                 : Wz[(k0 + k) * E_ + gc - E_];
        }
        __syncthreads();
#pragma unroll
        for (int k = 0; k < BK; k++) {
            float a[4], bb[4];
#pragma unroll
            for (int i = 0; i < 4; i++) a[i]  = As[k][ty * 4 + i];
#pragma unroll
            for (int i = 0; i < 4; i++) bb[i] = Bs[k][tx * 4 + i];
#pragma unroll
            for (int i = 0; i < 4; i++)
#pragma unroll
                for (int j = 0; j < 4; j++) acc[i][j] += a[i] * bb[j];
        }
        __syncthreads();
    }
#pragma unroll
    for (int i = 0; i < 4; i++) {
        int row = bm + ty * 4 + i;
#pragma unroll
        for (int j = 0; j < 4; j++) {
            int gc = bn + tx * 4 + j;
            float v = acc[i][j];
            if (gc < E_) {
                g_x[row * E_ + gc] = v + bx[gc];
            } else {
                int e = gc - E_;
                float z = v + bz[e];
                float s = z * sigmoidf_(z);       // silu
                g_gate[row * E_ + e] = sigmoidf_(s);
            }
        }
    }
}

// ---------------- K3: depthwise conv (dir-aware index remap) ------------------
// xc[step j] = cb[e] + sum_k cw[e,k] * x[pos(j-1+k)], pos = identity (fwd) or flip (bwd)
__global__ void conv_kernel(const float* __restrict__ cw,
                            const float* __restrict__ cb, int rev) {
    int idx = blockIdx.x * blockDim.x + threadIdx.x;
    if (idx >= RE_) return;
    int e = idx % E_;
    int r = idx / E_;
    int j = r & (J_ - 1);
    int b = r >> 10;
    float acc = cb[e];
#pragma unroll
    for (int k = 0; k < 3; k++) {
        int i = j - 1 + k;
        if (i >= 0 && i < J_) {
            int p = rev ? (J_ - 1 - i) : i;
            acc += cw[e * 3 + k] * g_x[(b * J_ + p) * E_ + e];
        }
    }
    g_xc[idx] = acc;
}

// ---------------- K4: projection GEMM xc @ [WB|WC|WD|Wi]  (N=64, K=384) -------
// Output written TRANSPOSED as g_bcdu[b][c][j] for coalesced scan reads.
__global__ void gemm_proj_kernel(const float* __restrict__ WB, const float* __restrict__ bB,
                                 const float* __restrict__ WC, const float* __restrict__ bC,
                                 const float* __restrict__ WD, const float* __restrict__ bD,
                                 const float* __restrict__ Wi, const float* __restrict__ bi) {
    const int BM = 64, BN = 64, BK = 32;
    __shared__ float As[BK][BM + 1];
    __shared__ float Bs[BK][BN];
    const float* Wp[4] = {WB, WC, WD, Wi};
    const float* bp[4] = {bB, bC, bD, bi};
    int bm = blockIdx.y * BM;
    int tid = threadIdx.x;
    int tx = tid & 15, ty = tid >> 4;
    float acc[4][4] = {};
    for (int k0 = 0; k0 < E_; k0 += BK) {
#pragma unroll
        for (int i = tid; i < BM * BK; i += 256) {
            int m = i >> 5, k = i & 31;
            As[k][m] = g_xc[(bm + m) * E_ + k0 + k];
        }
#pragma unroll
        for (int i = tid; i < BK * BN; i += 256) {
            int k = i >> 6, c = i & 63;
            Bs[k][c] = Wp[c >> 4][(k0 + k) * N_ + (c & 15)];
        }
        __syncthreads();
#pragma unroll
        for (int k = 0; k < BK; k++) {
            float a[4], bb[4];
#pragma unroll
            for (int i = 0; i < 4; i++) a[i]  = As[k][ty * 4 + i];
#pragma unroll
            for (int i = 0; i < 4; i++) bb[i] = Bs[k][tx * 4 + i];
#pragma unroll
            for (int i = 0; i < 4; i++)
#pragma unroll
                for (int j = 0; j < 4; j++) acc[i][j] += a[i] * bb[j];
        }
        __syncthreads();
    }
#pragma unroll
    for (int i = 0; i < 4; i++) {
        int row = bm + ty * 4 + i;
        int b = row >> 10, j = row & (J_ - 1);
#pragma unroll
        for (int jj = 0; jj < 4; jj++) {
            int c = tx * 4 + jj;
            float v = acc[i][jj] + bp[c >> 4][c & 15];
            g_bcdu[(b * 64 + c) * J_ + j] = v;
        }
    }
}

// ---------------- K5: selective scan (one block per (b,n)) --------------------
// 128 threads x 8 serial steps + Kogge-Stone block scan on (prod, partial) pairs.
__global__ void scan_kernel(const float* __restrict__ A_log, int rev) {
    int b = blockIdx.x >> 4;
    int n = blockIdx.x & 15;
    int t = threadIdx.x;
    float An = -softplusf(A_log[n]);
    float inv_den = 1.f / (An + 1e-6f);
    const float* base = g_bcdu + b * 64 * J_;
    const float* Bt = base + (0  + n) * J_;
    const float* Ct = base + (16 + n) * J_;
    const float* Dr = base + (32 + n) * J_;
    const float* Ut = base + (48 + n) * J_;

    int j0 = t * 8;
    float hl[8], pp[8], cc[8];
    float P = 1.f, S = 0.f;
#pragma unroll
    for (int i = 0; i < 8; i++) {
        int j = j0 + i;
        float dt = softplusf(Dr[j]);
        float ab = expf(dt * An);
        float bu = (ab - 1.f) * inv_den * Bt[j] * Ut[j];
        S = ab * S + bu;
        P = P * ab;
        hl[i] = S;
        pp[i] = P;
        cc[i] = Ct[j];
    }

    __shared__ float sP[128], sS[128];
    float iP = P, iS = S;
    for (int off = 1; off < 128; off <<= 1) {
        sP[t] = iP; sS[t] = iS;
        __syncthreads();
        if (t >= off) {
            float qP = sP[t - off], qS = sS[t - off];
            iS = qS * iP + iS;
            iP = qP * iP;
        }
        __syncthreads();
    }
    sS[t] = iS;
    __syncthreads();
    float Hin = (t == 0) ? 0.f : sS[t - 1];

#pragma unroll
    for (int i = 0; i < 8; i++) {
        int j = j0 + i;
        float h = hl[i] + pp[i] * Hin;
        float sc = h * cc[i];
        int pos = rev ? (J_ - 1 - j) : j;
        int oidx = (b * J_ + pos) * N_ + n;
        if (rev) g_S[oidx] += sc;   // kernels are stream-ordered: no race
        else     g_S[oidx]  = sc;
    }
}

// ---------------- K6: readout (K=16 dot) + 2*br + gate ------------------------
__global__ void readout_kernel(const float* __restrict__ Wr,
                               const float* __restrict__ br) {
    int idx = blockIdx.x * blockDim.x + threadIdx.x;
    if (idx >= RE_) return;
    int e = idx % E_;
    int r = idx / E_;
    const float* s = g_S + r * N_;
    float acc = 0.f;
#pragma unroll
    for (int n = 0; n < N_; n++) acc += s[n] * Wr[n * E_ + e];
    g_y[idx] = (acc + 2.f * br[e]) * g_gate[idx];
}

// ---------------- K7: output GEMM y @ Wo + bo + tokens ------------------------
__global__ void gemm_out_kernel(const float* __restrict__ Wo,
                                const float* __restrict__ bo,
                                const float* __restrict__ tokens,
                                float* __restrict__ out) {
    const int BM = 64, BN = 64, BK = 32;
    __shared__ float As[BK][BM + 1];
    __shared__ float Bs[BK][BN];
    int bm = blockIdx.y * BM;
    int bn = blockIdx.x * BN;
    int tid = threadIdx.x;
    int tx = tid & 15, ty = tid >> 4;
    float acc[4][4] = {};
    for (int k0 = 0; k0 < E_; k0 += BK) {
#pragma unroll
        for (int i = tid; i < BM * BK; i += 256) {
            int m = i >> 5, k = i & 31;
            As[k][m] = g_y[(bm + m) * E_ + k0 + k];
        }
#pragma unroll
        for (int i = tid; i < BK * BN; i += 256) {
            int k = i >> 6, c = i & 63;
            Bs[k][c] = Wo[(k0 + k) * D_ + bn + c];
        }
        __syncthreads();
#pragma unroll
        for (int k = 0; k < BK; k++) {
            float a[4], bb[4];
#pragma unroll
            for (int i = 0; i < 4; i++) a[i]  = As[k][ty * 4 + i];
#pragma unroll
            for (int i = 0; i < 4; i++) bb[i] = Bs[k][tx * 4 + i];
#pragma unroll
            for (int i = 0; i < 4; i++)
#pragma unroll
                for (int j = 0; j < 4; j++) acc[i][j] += a[i] * bb[j];
        }
        __syncthreads();
    }
#pragma unroll
    for (int i = 0; i < 4; i++) {
        int row = bm + ty * 4 + i;
#pragma unroll
        for (int j = 0; j < 4; j++) {
            int gc = bn + tx * 4 + j;
            out[row * D_ + gc] = tokens[row * D_ + gc] + acc[i][j] + bo[gc];
        }
    }
}

// ---------------- launcher ----------------------------------------------------
extern "C" void kernel_launch(void* const* d_in, const int* in_sizes, int n_in,
                              void* d_out, int out_size) {
    const float* tokens  = (const float*)d_in[0];
    const float* norm_g  = (const float*)d_in[1];
    const float* norm_b  = (const float*)d_in[2];
    const float* Wx      = (const float*)d_in[3];
    const float* bx      = (const float*)d_in[4];
    const float* Wz      = (const float*)d_in[5];
    const float* bz      = (const float*)d_in[6];
    const float* convf_w = (const float*)d_in[7];
    const float* convf_b = (const float*)d_in[8];
    const float* convb_w = (const float*)d_in[9];
    const float* convb_b = (const float*)d_in[10];
    const float* WBf = (const float*)d_in[11];
    const float* bBf = (const float*)d_in[12];
    const float* WCf = (const float*)d_in[13];
    const float* bCf = (const float*)d_in[14];
    const float* WDf = (const float*)d_in[15];
    const float* bDf = (const float*)d_in[16];
    const float* WBb = (const float*)d_in[17];
    const float* bBb = (const float*)d_in[18];
    const float* WCb = (const float*)d_in[19];
    const float* bCb = (const float*)d_in[20];
    const float* WDb = (const float*)d_in[21];
    const float* bDb = (const float*)d_in[22];
    const float* A_log = (const float*)d_in[23];
    const float* Wi  = (const float*)d_in[24];
    const float* bi  = (const float*)d_in[25];
    const float* Wr  = (const float*)d_in[26];
    const float* br  = (const float*)d_in[27];
    const float* Wo  = (const float*)d_in[28];
    const float* bo  = (const float*)d_in[29];
    float* out = (float*)d_out;

    // K1: LayerNorm (8 warps per block)
    ln_kernel<<<R_ / 8, 256>>>(tokens, norm_g, norm_b);

    // K2: x,z projections (N=768)
    gemm_xz_kernel<<<dim3(12, R_ / 64), 256>>>(Wx, bx, Wz, bz);

    const int ethreads = 256;
    const int eblocks = RE_ / ethreads;

    // Forward direction
    conv_kernel<<<eblocks, ethreads>>>(convf_w, convf_b, 0);
    gemm_proj_kernel<<<dim3(1, R_ / 64), 256>>>(WBf, bBf, WCf, bCf, WDf, bDf, Wi, bi);
    scan_kernel<<<B_ * N_, 128>>>(A_log, 0);

    // Backward direction
    conv_kernel<<<eblocks, ethreads>>>(convb_w, convb_b, 1);
    gemm_proj_kernel<<<dim3(1, R_ / 64), 256>>>(WBb, bBb, WCb, bCb, WDb, bDb, Wi, bi);
    scan_kernel<<<B_ * N_, 128>>>(A_log, 1);

    // Readout + gate
    readout_kernel<<<eblocks, ethreads>>>(Wr, br);

    // Output projection + residual
    gemm_out_kernel<<<dim3(3, R_ / 64), 256>>>(Wo, bo, tokens, out);
}